// round 14
// baseline (speedup 1.0000x reference)
#include <cuda_runtime.h>
#include <math.h>

#define NB 512
#define DMODEL 2048
#define NH 8
#define DMEM 128
#define NM 512
#define KPROJ_N 1024     // H*DMEM
#define VPROJ_N 2048     // 2*H*DMEM
#define MEM_ELEMS (NB*NM*DMEM)

// Scratch (device globals: no allocation allowed)
__device__ float g_ak[NB * KPROJ_N];
__device__ float g_v [NB * VPROJ_N];
__device__ float g_aq[NM * DMEM];
__device__ float g_si[NM * DMEM];
__device__ float g_S [NB * NM * NH];

__device__ __forceinline__ float actf(float x) {
    return x > 0.f ? x + 1.f : __expf(x);   // elu(x)+1
}
__device__ __forceinline__ float sigm(float x) {
    return 1.f / (1.f + __expf(-x));
}
__device__ __forceinline__ void cp16(void* s, const void* g) {
    unsigned sa = (unsigned)__cvta_generic_to_shared(s);
    asm volatile("cp.async.cg.shared.global [%0], [%1], 16;\n" :: "r"(sa), "l"(g));
}
__device__ __forceinline__ void cp4(void* s, const void* g) {
    unsigned sa = (unsigned)__cvta_generic_to_shared(s);
    asm volatile("cp.async.ca.shared.global [%0], [%1], 4;\n" :: "r"(sa), "l"(g));
}
#define CP_COMMIT() asm volatile("cp.async.commit_group;\n" ::: "memory")
#define CP_WAIT(n)  asm volatile("cp.async.wait_group %0;\n" :: "n"(n) : "memory")

// ---------------------------------------------------------------------------
// K0: aq = act(addresses), si = sigmoid(interpolation_logits)
// ---------------------------------------------------------------------------
__global__ void prep_kernel(const float* __restrict__ addresses,
                            const float* __restrict__ interp) {
    int i = blockIdx.x * blockDim.x + threadIdx.x;
    if (i < NM * DMEM) {
        g_aq[i] = actf(addresses[i]);
        g_si[i] = sigm(interp[i]);
    }
}

// ---------------------------------------------------------------------------
// K1: fused projection GEMMs via mma.sync tf32 (m16n8k8)
//   BM=64 BN=64 BK=32, 256 threads (8 warps, 2x4), warp tile 32x16.
//   2-stage cp.async pipeline (37KB smem) + launch_bounds(256,3):
//   3 CTAs/SM -> 384 CTAs in ONE wave (R13 at 2 CTAs/SM had a 40%-idle
//   second wave), 24 warps/SM to cover wait/barrier stalls.
// ---------------------------------------------------------------------------
#define BM 64
#define BN 64
#define BK 32
#define PADA 36
#define PADB 72
#define PSTG 2

__global__ __launch_bounds__(256, 3) void proj_mma_kernel(
    const float* __restrict__ key, const float* __restrict__ values,
    const float* __restrict__ W_key, const float* __restrict__ b_key,
    const float* __restrict__ W_val, const float* __restrict__ b_val)
{
    const float *A, *W, *bias;
    float* C;
    int N, doact;
    int bx = blockIdx.x;
    if (bx < KPROJ_N / BN) { A = key;    W = W_key; bias = b_key; C = g_ak; N = KPROJ_N; doact = 1; }
    else { bx -= KPROJ_N / BN; A = values; W = W_val; bias = b_val; C = g_v; N = VPROJ_N; doact = 0; }

    __shared__ float As[PSTG][BM][PADA];   // [stage][m][k]
    __shared__ float Bs[PSTG][BK][PADB];   // [stage][k][n]

    int t = threadIdx.x;
    int lane = t & 31;
    int warp = t >> 5;
    int g  = lane >> 2;
    int tg = lane & 3;
    int wm = (warp & 1) * 32;
    int wn = (warp >> 1) * 16;
    int bm0 = blockIdx.y * BM;
    int bn0 = bx * BN;

    float acc[2][2][4];
    #pragma unroll
    for (int i = 0; i < 2; i++)
        #pragma unroll
        for (int j = 0; j < 2; j++)
            #pragma unroll
            for (int r = 0; r < 4; r++) acc[i][j][r] = 0.f;

    int ar0 = t >> 3,        ac0 = (t & 7) * 4;     // A rows 0..31
    int ar1 = ar0 + 32;                              // A rows 32..63
    int bk0 = t >> 4,        bn4 = (t & 15) * 4;    // B k 0..15

    const float* Ab = A + (size_t)bm0 * DMODEL;
    const int NKT = DMODEL / BK;   // 64

    // prologue: stage 0
    cp16(&As[0][ar0][ac0], Ab + (size_t)ar0 * DMODEL + ac0);
    cp16(&As[0][ar1][ac0], Ab + (size_t)ar1 * DMODEL + ac0);
    cp16(&Bs[0][bk0][bn4],      W + (size_t)bk0 * N + bn0 + bn4);
    cp16(&Bs[0][bk0 + 16][bn4], W + (size_t)(bk0 + 16) * N + bn0 + bn4);
    CP_COMMIT();

    for (int kt = 0; kt < NKT; kt++) {
        CP_WAIT(0);              // tile kt has arrived
        __syncthreads();         // also orders the prefetch below (into the
                                 // buffer computed at iter kt-1) after that compute

        int kp = kt + 1;
        if (kp < NKT) {
            int sp = kp & 1;
            int k0 = kp * BK;
            cp16(&As[sp][ar0][ac0], Ab + (size_t)ar0 * DMODEL + k0 + ac0);
            cp16(&As[sp][ar1][ac0], Ab + (size_t)ar1 * DMODEL + k0 + ac0);
            cp16(&Bs[sp][bk0][bn4],      W + (size_t)(k0 + bk0) * N + bn0 + bn4);
            cp16(&Bs[sp][bk0 + 16][bn4], W + (size_t)(k0 + bk0 + 16) * N + bn0 + bn4);
        }
        CP_COMMIT();             // empty groups retire free on the last iter

        int buf = kt & 1;
        #pragma unroll
        for (int ks = 0; ks < 4; ks++) {
            int kk = ks * 8;
            unsigned a[2][4], b[2][2];
            #pragma unroll
            for (int ms = 0; ms < 2; ms++) {
                int m = wm + ms * 16 + g;
                a[ms][0] = __float_as_uint(As[buf][m    ][kk + tg    ]);
                a[ms][1] = __float_as_uint(As[buf][m + 8][kk + tg    ]);
                a[ms][2] = __float_as_uint(As[buf][m    ][kk + tg + 4]);
                a[ms][3] = __float_as_uint(As[buf][m + 8][kk + tg + 4]);
            }
            #pragma unroll
            for (int ns = 0; ns < 2; ns++) {
                int n = wn + ns * 8 + g;
                b[ns][0] = __float_as_uint(Bs[buf][kk + tg    ][n]);
                b[ns][1] = __float_as_uint(Bs[buf][kk + tg + 4][n]);
            }
            #pragma unroll
            for (int ms = 0; ms < 2; ms++)
                #pragma unroll
                for (int ns = 0; ns < 2; ns++) {
                    asm volatile(
                        "mma.sync.aligned.m16n8k8.row.col.f32.tf32.tf32.f32 "
                        "{%0,%1,%2,%3}, {%4,%5,%6,%7}, {%8,%9}, {%0,%1,%2,%3};\n"
                        : "+f"(acc[ms][ns][0]), "+f"(acc[ms][ns][1]),
                          "+f"(acc[ms][ns][2]), "+f"(acc[ms][ns][3])
                        : "r"(a[ms][0]), "r"(a[ms][1]), "r"(a[ms][2]), "r"(a[ms][3]),
                          "r"(b[ns][0]), "r"(b[ns][1]));
                }
        }
    }

    #pragma unroll
    for (int ms = 0; ms < 2; ms++) {
        int row0 = bm0 + wm + ms * 16 + g;
        #pragma unroll
        for (int ns = 0; ns < 2; ns++) {
            int col = bn0 + wn + ns * 8 + 2 * tg;
            float b0 = bias[col], b1 = bias[col + 1];
            float o0 = acc[ms][ns][0] + b0;
            float o1 = acc[ms][ns][1] + b1;
            float o2 = acc[ms][ns][2] + b0;
            float o3 = acc[ms][ns][3] + b1;
            if (doact) { o0 = actf(o0); o1 = actf(o1); o2 = actf(o2); o3 = actf(o3); }
            float2 lo = {o0, o1}, hi = {o2, o3};
            *(float2*)(C + (size_t)row0 * N + col)       = lo;
            *(float2*)(C + (size_t)(row0 + 8) * N + col) = hi;
        }
    }
}

// ---------------------------------------------------------------------------
// K2: S[b,m,h] = sum_d aq[m,d] * ak[b,h,d]
// ---------------------------------------------------------------------------
__global__ __launch_bounds__(256) void s_kernel() {
    int b  = blockIdx.y;
    int m0 = blockIdx.x * 32;
    __shared__ float ak_s[8][132];
    __shared__ float aq_s[32][132];
    int t = threadIdx.x;
    {
        int h = t >> 5, d4 = (t & 31) * 4;
        float4 v = *(const float4*)&g_ak[b * KPROJ_N + h * DMEM + d4];
        *(float4*)&ak_s[h][d4] = v;
    }
    #pragma unroll
    for (int i = 0; i < 4; i++) {
        int idx = t + i * 256;
        int ml = idx >> 5, d4 = (idx & 31) * 4;
        float4 v = *(const float4*)&g_aq[(m0 + ml) * DMEM + d4];
        *(float4*)&aq_s[ml][d4] = v;
    }
    __syncthreads();
    int ml = t >> 3, h = t & 7;
    float s = 0.f;
    #pragma unroll
    for (int d4 = 0; d4 < 32; d4++) {
        float4 a = *(const float4*)&aq_s[ml][d4 * 4];
        float4 k = *(const float4*)&ak_s[h][d4 * 4];
        s += a.x * k.x + a.y * k.y + a.z * k.z + a.w * k.w;
    }
    g_S[(b * NM + m0 + ml) * NH + h] = s;
}

// ---------------------------------------------------------------------------
// K3: epilogue (frozen from R13: 96.2us, occ 32.9%, DRAM 66.6%)
// ---------------------------------------------------------------------------
__global__ __launch_bounds__(256, 3) void epilogue_kernel(
    const float* __restrict__ memories, const float* __restrict__ write_mass,
    const unsigned char* __restrict__ batch_mask, float* __restrict__ out)
{
    int b  = blockIdx.y;
    int m0 = blockIdx.x * 32;
    __shared__ float4 v_s[NH * 64];      // 8 KB  v[h][e4]
    __shared__ float  S_s[256];          // 1 KB  S[row*8+h]
    __shared__ float4 si_s[32 * 32];     // 16 KB [row][d4]
    __shared__ float4 mem_s[32 * 32];    // 16 KB
    __shared__ float4 wm_s [32 * 32];    // 16 KB
    int t = threadIdx.x;
    int ml = t >> 5;
    int d4 = t & 31;
    int r0 = ml * 4;

    unsigned char msk = batch_mask[b];

    // group A: v + S + si (needed by compute / wf phase)
    const float4* gv = (const float4*)(g_v + (size_t)b * VPROJ_N);
    cp16(&v_s[t],       &gv[t]);
    cp16(&v_s[t + 256], &gv[t + 256]);
    cp4(&S_s[t], &g_S[((size_t)b * NM + m0) * NH + t]);
    #pragma unroll
    for (int i = 0; i < 4; i++) {
        int row = r0 + i;
        cp16(&si_s[row * 32 + d4], &g_si[(m0 + row) * DMEM + d4 * 4]);
    }
    CP_COMMIT();

    // group B: memories + write_mass (needed only at tail)
    #pragma unroll
    for (int i = 0; i < 4; i++) {
        int row = r0 + i;
        size_t base = ((size_t)b * NM + m0 + row) * DMEM + d4 * 4;
        cp16(&mem_s[row * 32 + d4], &memories[base]);
        cp16(&wm_s [row * 32 + d4], &write_mass[base]);
    }
    CP_COMMIT();

    CP_WAIT(1);          // group A done
    __syncthreads();

    float dn[4] = {1e-5f, 1e-5f, 1e-5f, 1e-5f};

    // pass 1: write-logit accumulation (reads only lower half of v)
    float4 aL[4];
    #pragma unroll
    for (int i = 0; i < 4; i++) aL[i] = make_float4(0.f, 0.f, 0.f, 0.f);
    #pragma unroll
    for (int h = 0; h < 8; h++) {
        float4 vl = v_s[h * 64 + 32 + d4];
        #pragma unroll
        for (int i = 0; i < 4; i++) {
            float s = S_s[(r0 + i) * 8 + h];
            dn[i] += s;
            aL[i].x = fmaf(s, vl.x, aL[i].x); aL[i].y = fmaf(s, vl.y, aL[i].y);
            aL[i].z = fmaf(s, vl.z, aL[i].z); aL[i].w = fmaf(s, vl.w, aL[i].w);
        }
    }

    // wf (aL registers die here)
    float rdv[4];
    float4 wf[4];
    #pragma unroll
    for (int i = 0; i < 4; i++) {
        rdv[i] = __fdividef(1.f, dn[i]);
        float4 si = si_s[(r0 + i) * 32 + d4];
        wf[i].x = 0.7f * sigm(aL[i].x * rdv[i]) * si.x;
        wf[i].y = 0.7f * sigm(aL[i].y * rdv[i]) * si.y;
        wf[i].z = 0.7f * sigm(aL[i].z * rdv[i]) * si.z;
        wf[i].w = 0.7f * sigm(aL[i].w * rdv[i]) * si.w;
    }

    // pass 2: update accumulation (reads only upper half of v)
    float4 aU[4];
    #pragma unroll
    for (int i = 0; i < 4; i++) aU[i] = make_float4(0.f, 0.f, 0.f, 0.f);
    #pragma unroll
    for (int h = 0; h < 8; h++) {
        float4 vu = v_s[h * 64 + d4];
        #pragma unroll
        for (int i = 0; i < 4; i++) {
            float s = S_s[(r0 + i) * 8 + h];
            aU[i].x = fmaf(s, vu.x, aU[i].x); aU[i].y = fmaf(s, vu.y, aU[i].y);
            aU[i].z = fmaf(s, vu.z, aU[i].z); aU[i].w = fmaf(s, vu.w, aU[i].w);
        }
    }

    CP_WAIT(0);          // group B done
    __syncthreads();

    #pragma unroll
    for (int i = 0; i < 4; i++) {
        int row = r0 + i;
        size_t base = ((size_t)b * NM + m0 + row) * DMEM + d4 * 4;
        float4 mem = mem_s[row * 32 + d4];
        float4 wm4 = wm_s [row * 32 + d4];

        float4 om, oa;
        if (msk) {
            om = mem; oa = wm4;
        } else {
            om.x = mem.x + wf[i].x * (aU[i].x * rdv[i] - mem.x);
            om.y = mem.y + wf[i].y * (aU[i].y * rdv[i] - mem.y);
            om.z = mem.z + wf[i].z * (aU[i].z * rdv[i] - mem.z);
            om.w = mem.w + wf[i].w * (aU[i].w * rdv[i] - mem.w);
            oa.x = wm4.x + wf[i].x; oa.y = wm4.y + wf[i].y;
            oa.z = wm4.z + wf[i].z; oa.w = wm4.w + wf[i].w;
        }
        *(float4*)&out[base] = om;
        *(float4*)&out[MEM_ELEMS + base] = oa;
    }
}

// ---------------------------------------------------------------------------
extern "C" void kernel_launch(void* const* d_in, const int* in_sizes, int n_in,
                              void* d_out, int out_size) {
    const float* key        = (const float*)d_in[0];
    const float* values     = (const float*)d_in[1];
    const float* memories   = (const float*)d_in[2];
    const float* write_mass = (const float*)d_in[3];
    const unsigned char* batch_mask = (const unsigned char*)d_in[4];
    const float* W_key      = (const float*)d_in[5];
    const float* b_key      = (const float*)d_in[6];
    const float* W_val      = (const float*)d_in[7];
    const float* b_val      = (const float*)d_in[8];
    const float* addresses  = (const float*)d_in[9];
    const float* interp     = (const float*)d_in[10];
    float* out = (float*)d_out;

    prep_kernel<<<256, 256>>>(addresses, interp);
    proj_mma_kernel<<<dim3((KPROJ_N + VPROJ_N) / BN, NB / BM), 256>>>(
        key, values, W_key, b_key, W_val, b_val);
    s_kernel<<<dim3(NM / 32, NB), 256>>>();
    epilogue_kernel<<<dim3(NM / 32, NB), 256>>>(memories, write_mass, batch_mask, out);
}

// round 16
// speedup vs baseline: 1.0333x; 1.0333x over previous
#include <cuda_runtime.h>
#include <math.h>

#define NB 512
#define DMODEL 2048
#define NH 8
#define DMEM 128
#define NM 512
#define KPROJ_N 1024     // H*DMEM
#define VPROJ_N 2048     // 2*H*DMEM
#define MEM_ELEMS (NB*NM*DMEM)

// Scratch (device globals: no allocation allowed)
__device__ float g_ak[NB * KPROJ_N];
__device__ float g_v [NB * VPROJ_N];
__device__ float g_aq[NM * DMEM];
__device__ float g_si[NM * DMEM];
__device__ float g_S [NB * NM * NH];

__device__ __forceinline__ float actf(float x) {
    return x > 0.f ? x + 1.f : __expf(x);   // elu(x)+1
}
__device__ __forceinline__ float sigm(float x) {
    return 1.f / (1.f + __expf(-x));
}
__device__ __forceinline__ void cp16(void* s, const void* g) {
    unsigned sa = (unsigned)__cvta_generic_to_shared(s);
    asm volatile("cp.async.cg.shared.global [%0], [%1], 16;\n" :: "r"(sa), "l"(g));
}
__device__ __forceinline__ void cp4(void* s, const void* g) {
    unsigned sa = (unsigned)__cvta_generic_to_shared(s);
    asm volatile("cp.async.ca.shared.global [%0], [%1], 4;\n" :: "r"(sa), "l"(g));
}
#define CP_COMMIT() asm volatile("cp.async.commit_group;\n" ::: "memory")
#define CP_WAIT(n)  asm volatile("cp.async.wait_group %0;\n" :: "n"(n) : "memory")

// ---------------------------------------------------------------------------
// K0: aq = act(addresses), si = sigmoid(interpolation_logits)
// ---------------------------------------------------------------------------
__global__ void prep_kernel(const float* __restrict__ addresses,
                            const float* __restrict__ interp) {
    int i = blockIdx.x * blockDim.x + threadIdx.x;
    if (i < NM * DMEM) {
        g_aq[i] = actf(addresses[i]);
        g_si[i] = sigm(interp[i]);
    }
}

// ---------------------------------------------------------------------------
// K1: fused projection GEMMs via mma.sync tf32 (m16n8k8)
//   BM=64 BN=64 BK=32, 256 threads (8 warps, 2x4), warp tile 32x16.
//   R13's 3-stage cp.async pipeline (2 tiles in flight, CP_WAIT(1))
//   + launch_bounds(256,3): 3 CTAs/SM -> single wave (R14's 2-stage
//   exposed full tile latency each iter; R13 lacked the occupancy).
//   [R15 bench was an infra failure; re-running this config unchanged.]
// ---------------------------------------------------------------------------
#define BM 64
#define BN 64
#define BK 32
#define PADA 36
#define PADB 72
#define PSTG 3

__global__ __launch_bounds__(256, 3) void proj_mma_kernel(
    const float* __restrict__ key, const float* __restrict__ values,
    const float* __restrict__ W_key, const float* __restrict__ b_key,
    const float* __restrict__ W_val, const float* __restrict__ b_val)
{
    const float *A, *W, *bias;
    float* C;
    int N, doact;
    int bx = blockIdx.x;
    if (bx < KPROJ_N / BN) { A = key;    W = W_key; bias = b_key; C = g_ak; N = KPROJ_N; doact = 1; }
    else { bx -= KPROJ_N / BN; A = values; W = W_val; bias = b_val; C = g_v; N = VPROJ_N; doact = 0; }

    __shared__ float As[PSTG][BM][PADA];   // [stage][m][k]
    __shared__ float Bs[PSTG][BK][PADB];   // [stage][k][n]

    int t = threadIdx.x;
    int lane = t & 31;
    int warp = t >> 5;
    int g  = lane >> 2;
    int tg = lane & 3;
    int wm = (warp & 1) * 32;
    int wn = (warp >> 1) * 16;
    int bm0 = blockIdx.y * BM;
    int bn0 = bx * BN;

    float acc[2][2][4];
    #pragma unroll
    for (int i = 0; i < 2; i++)
        #pragma unroll
        for (int j = 0; j < 2; j++)
            #pragma unroll
            for (int r = 0; r < 4; r++) acc[i][j][r] = 0.f;

    int ar0 = t >> 3,        ac0 = (t & 7) * 4;     // A rows 0..31
    int ar1 = ar0 + 32;                              // A rows 32..63
    int bk0 = t >> 4,        bn4 = (t & 15) * 4;    // B k 0..15

    const float* Ab = A + (size_t)bm0 * DMODEL;
    const int NKT = DMODEL / BK;   // 64

    // prologue: stages 0..PSTG-2
    #pragma unroll
    for (int s = 0; s < PSTG - 1; s++) {
        int k0 = s * BK;
        cp16(&As[s][ar0][ac0], Ab + (size_t)ar0 * DMODEL + k0 + ac0);
        cp16(&As[s][ar1][ac0], Ab + (size_t)ar1 * DMODEL + k0 + ac0);
        cp16(&Bs[s][bk0][bn4],      W + (size_t)(k0 + bk0) * N + bn0 + bn4);
        cp16(&Bs[s][bk0 + 16][bn4], W + (size_t)(k0 + bk0 + 16) * N + bn0 + bn4);
        CP_COMMIT();
    }

    for (int kt = 0; kt < NKT; kt++) {
        CP_WAIT(PSTG - 2);       // tile kt has arrived (one tile still in flight)
        __syncthreads();         // one barrier per iter: also orders the write
                                 // below into stage (kt-1)%PSTG after its compute

        int kp = kt + PSTG - 1;
        if (kp < NKT) {
            int sp = kp % PSTG;
            int k0 = kp * BK;
            cp16(&As[sp][ar0][ac0], Ab + (size_t)ar0 * DMODEL + k0 + ac0);
            cp16(&As[sp][ar1][ac0], Ab + (size_t)ar1 * DMODEL + k0 + ac0);
            cp16(&Bs[sp][bk0][bn4],      W + (size_t)(k0 + bk0) * N + bn0 + bn4);
            cp16(&Bs[sp][bk0 + 16][bn4], W + (size_t)(k0 + bk0 + 16) * N + bn0 + bn4);
        }
        CP_COMMIT();             // commit every iter (empty groups retire free)

        int buf = kt % PSTG;
        #pragma unroll
        for (int ks = 0; ks < 4; ks++) {
            int kk = ks * 8;
            unsigned a[2][4], b[2][2];
            #pragma unroll
            for (int ms = 0; ms < 2; ms++) {
                int m = wm + ms * 16 + g;
                a[ms][0] = __float_as_uint(As[buf][m    ][kk + tg    ]);
                a[ms][1] = __float_as_uint(As[buf][m + 8][kk + tg    ]);
                a[ms][2] = __float_as_uint(As[buf][m    ][kk + tg + 4]);
                a[ms][3] = __float_as_uint(As[buf][m + 8][kk + tg + 4]);
            }
            #pragma unroll
            for (int ns = 0; ns < 2; ns++) {
                int n = wn + ns * 8 + g;
                b[ns][0] = __float_as_uint(Bs[buf][kk + tg    ][n]);
                b[ns][1] = __float_as_uint(Bs[buf][kk + tg + 4][n]);
            }
            #pragma unroll
            for (int ms = 0; ms < 2; ms++)
                #pragma unroll
                for (int ns = 0; ns < 2; ns++) {
                    asm volatile(
                        "mma.sync.aligned.m16n8k8.row.col.f32.tf32.tf32.f32 "
                        "{%0,%1,%2,%3}, {%4,%5,%6,%7}, {%8,%9}, {%0,%1,%2,%3};\n"
                        : "+f"(acc[ms][ns][0]), "+f"(acc[ms][ns][1]),
                          "+f"(acc[ms][ns][2]), "+f"(acc[ms][ns][3])
                        : "r"(a[ms][0]), "r"(a[ms][1]), "r"(a[ms][2]), "r"(a[ms][3]),
                          "r"(b[ns][0]), "r"(b[ns][1]));
                }
        }
    }

    #pragma unroll
    for (int ms = 0; ms < 2; ms++) {
        int row0 = bm0 + wm + ms * 16 + g;
        #pragma unroll
        for (int ns = 0; ns < 2; ns++) {
            int col = bn0 + wn + ns * 8 + 2 * tg;
            float b0 = bias[col], b1 = bias[col + 1];
            float o0 = acc[ms][ns][0] + b0;
            float o1 = acc[ms][ns][1] + b1;
            float o2 = acc[ms][ns][2] + b0;
            float o3 = acc[ms][ns][3] + b1;
            if (doact) { o0 = actf(o0); o1 = actf(o1); o2 = actf(o2); o3 = actf(o3); }
            float2 lo = {o0, o1}, hi = {o2, o3};
            *(float2*)(C + (size_t)row0 * N + col)       = lo;
            *(float2*)(C + (size_t)(row0 + 8) * N + col) = hi;
        }
    }
}

// ---------------------------------------------------------------------------
// K2: S[b,m,h] = sum_d aq[m,d] * ak[b,h,d]
// ---------------------------------------------------------------------------
__global__ __launch_bounds__(256) void s_kernel() {
    int b  = blockIdx.y;
    int m0 = blockIdx.x * 32;
    __shared__ float ak_s[8][132];
    __shared__ float aq_s[32][132];
    int t = threadIdx.x;
    {
        int h = t >> 5, d4 = (t & 31) * 4;
        float4 v = *(const float4*)&g_ak[b * KPROJ_N + h * DMEM + d4];
        *(float4*)&ak_s[h][d4] = v;
    }
    #pragma unroll
    for (int i = 0; i < 4; i++) {
        int idx = t + i * 256;
        int ml = idx >> 5, d4 = (idx & 31) * 4;
        float4 v = *(const float4*)&g_aq[(m0 + ml) * DMEM + d4];
        *(float4*)&aq_s[ml][d4] = v;
    }
    __syncthreads();
    int ml = t >> 3, h = t & 7;
    float s = 0.f;
    #pragma unroll
    for (int d4 = 0; d4 < 32; d4++) {
        float4 a = *(const float4*)&aq_s[ml][d4 * 4];
        float4 k = *(const float4*)&ak_s[h][d4 * 4];
        s += a.x * k.x + a.y * k.y + a.z * k.z + a.w * k.w;
    }
    g_S[(b * NM + m0 + ml) * NH + h] = s;
}

// ---------------------------------------------------------------------------
// K3: epilogue (frozen: 96.2us, occ ~33%, DRAM 66.6%)
// ---------------------------------------------------------------------------
__global__ __launch_bounds__(256, 3) void epilogue_kernel(
    const float* __restrict__ memories, const float* __restrict__ write_mass,
    const unsigned char* __restrict__ batch_mask, float* __restrict__ out)
{
    int b  = blockIdx.y;
    int m0 = blockIdx.x * 32;
    __shared__ float4 v_s[NH * 64];      // 8 KB  v[h][e4]
    __shared__ float  S_s[256];          // 1 KB  S[row*8+h]
    __shared__ float4 si_s[32 * 32];     // 16 KB [row][d4]
    __shared__ float4 mem_s[32 * 32];    // 16 KB
    __shared__ float4 wm_s [32 * 32];    // 16 KB
    int t = threadIdx.x;
    int ml = t >> 5;
    int d4 = t & 31;
    int r0 = ml * 4;

    unsigned char msk = batch_mask[b];

    // group A: v + S + si (needed by compute / wf phase)
    const float4* gv = (const float4*)(g_v + (size_t)b * VPROJ_N);
    cp16(&v_s[t],       &gv[t]);
    cp16(&v_s[t + 256], &gv[t + 256]);
    cp4(&S_s[t], &g_S[((size_t)b * NM + m0) * NH + t]);
    #pragma unroll
    for (int i = 0; i < 4; i++) {
        int row = r0 + i;
        cp16(&si_s[row * 32 + d4], &g_si[(m0 + row) * DMEM + d4 * 4]);
    }
    CP_COMMIT();

    // group B: memories + write_mass (needed only at tail)
    #pragma unroll
    for (int i = 0; i < 4; i++) {
        int row = r0 + i;
        size_t base = ((size_t)b * NM + m0 + row) * DMEM + d4 * 4;
        cp16(&mem_s[row * 32 + d4], &memories[base]);
        cp16(&wm_s [row * 32 + d4], &write_mass[base]);
    }
    CP_COMMIT();

    CP_WAIT(1);          // group A done
    __syncthreads();

    float dn[4] = {1e-5f, 1e-5f, 1e-5f, 1e-5f};

    // pass 1: write-logit accumulation (reads only lower half of v)
    float4 aL[4];
    #pragma unroll
    for (int i = 0; i < 4; i++) aL[i] = make_float4(0.f, 0.f, 0.f, 0.f);
    #pragma unroll
    for (int h = 0; h < 8; h++) {
        float4 vl = v_s[h * 64 + 32 + d4];
        #pragma unroll
        for (int i = 0; i < 4; i++) {
            float s = S_s[(r0 + i) * 8 + h];
            dn[i] += s;
            aL[i].x = fmaf(s, vl.x, aL[i].x); aL[i].y = fmaf(s, vl.y, aL[i].y);
            aL[i].z = fmaf(s, vl.z, aL[i].z); aL[i].w = fmaf(s, vl.w, aL[i].w);
        }
    }

    // wf (aL registers die here)
    float rdv[4];
    float4 wf[4];
    #pragma unroll
    for (int i = 0; i < 4; i++) {
        rdv[i] = __fdividef(1.f, dn[i]);
        float4 si = si_s[(r0 + i) * 32 + d4];
        wf[i].x = 0.7f * sigm(aL[i].x * rdv[i]) * si.x;
        wf[i].y = 0.7f * sigm(aL[i].y * rdv[i]) * si.y;
        wf[i].z = 0.7f * sigm(aL[i].z * rdv[i]) * si.z;
        wf[i].w = 0.7f * sigm(aL[i].w * rdv[i]) * si.w;
    }

    // pass 2: update accumulation (reads only upper half of v)
    float4 aU[4];
    #pragma unroll
    for (int i = 0; i < 4; i++) aU[i] = make_float4(0.f, 0.f, 0.f, 0.f);
    #pragma unroll
    for (int h = 0; h < 8; h++) {
        float4 vu = v_s[h * 64 + d4];
        #pragma unroll
        for (int i = 0; i < 4; i++) {
            float s = S_s[(r0 + i) * 8 + h];
            aU[i].x = fmaf(s, vu.x, aU[i].x); aU[i].y = fmaf(s, vu.y, aU[i].y);
            aU[i].z = fmaf(s, vu.z, aU[i].z); aU[i].w = fmaf(s, vu.w, aU[i].w);
        }
    }

    CP_WAIT(0);          // group B done
    __syncthreads();

    #pragma unroll
    for (int i = 0; i < 4; i++) {
        int row = r0 + i;
        size_t base = ((size_t)b * NM + m0 + row) * DMEM + d4 * 4;
        float4 mem = mem_s[row * 32 + d4];
        float4 wm4 = wm_s [row * 32 + d4];

        float4 om, oa;
        if (msk) {
            om = mem; oa = wm4;
        } else {
            om.x = mem.x + wf[i].x * (aU[i].x * rdv[i] - mem.x);
            om.y = mem.y + wf[i].y * (aU[i].y * rdv[i] - mem.y);
            om.z = mem.z + wf[i].z * (aU[i].z * rdv[i] - mem.z);
            om.w = mem.w + wf[i].w * (aU[i].w * rdv[i] - mem.w);
            oa.x = wm4.x + wf[i].x; oa.y = wm4.y + wf[i].y;
            oa.z = wm4.z + wf[i].z; oa.w = wm4.w + wf[i].w;
        }
        *(float4*)&out[base] = om;
        *(float4*)&out[MEM_ELEMS + base] = oa;
    }
}

// ---------------------------------------------------------------------------
extern "C" void kernel_launch(void* const* d_in, const int* in_sizes, int n_in,
                              void* d_out, int out_size) {
    const float* key        = (const float*)d_in[0];
    const float* values     = (const float*)d_in[1];
    const float* memories   = (const float*)d_in[2];
    const float* write_mass = (const float*)d_in[3];
    const unsigned char* batch_mask = (const unsigned char*)d_in[4];
    const float* W_key      = (const float*)d_in[5];
    const float* b_key      = (const float*)d_in[6];
    const float* W_val      = (const float*)d_in[7];
    const float* b_val      = (const float*)d_in[8];
    const float* addresses  = (const float*)d_in[9];
    const float* interp     = (const float*)d_in[10];
    float* out = (float*)d_out;

    prep_kernel<<<256, 256>>>(addresses, interp);
    proj_mma_kernel<<<dim3((KPROJ_N + VPROJ_N) / BN, NB / BM), 256>>>(
        key, values, W_key, b_key, W_val, b_val);
    s_kernel<<<dim3(NM / 32, NB), 256>>>();
    epilogue_kernel<<<dim3(NM / 32, NB), 256>>>(memories, write_mass, batch_mask, out);
}

// round 17
// speedup vs baseline: 1.0863x; 1.0513x over previous
#include <cuda_runtime.h>
#include <cuda_bf16.h>
#include <math.h>

#define NB 512
#define DMODEL 2048
#define NH 8
#define DMEM 128
#define NM 512
#define KPROJ_N 1024     // H*DMEM
#define VPROJ_N 2048     // 2*H*DMEM
#define MEM_ELEMS (NB*NM*DMEM)

// Scratch (device globals: no allocation allowed)
__device__ float g_ak[NB * KPROJ_N];
__device__ float g_v [NB * VPROJ_N];
__device__ float g_aq[NM * DMEM];
__device__ float g_si[NM * DMEM];
__device__ float g_S [NB * NM * NH];
// bf16 staging for the projection GEMMs
__device__ __nv_bfloat16 g_kb [NB * DMODEL];          // key   -> bf16
__device__ __nv_bfloat16 g_vb [NB * DMODEL];          // values-> bf16
__device__ __nv_bfloat16 g_WkT[KPROJ_N * DMODEL];     // W_key^T  [n][k] bf16
__device__ __nv_bfloat16 g_WvT[VPROJ_N * DMODEL];     // W_val^T  [n][k] bf16

__device__ __forceinline__ float actf(float x) {
    return x > 0.f ? x + 1.f : __expf(x);   // elu(x)+1
}
__device__ __forceinline__ float sigm(float x) {
    return 1.f / (1.f + __expf(-x));
}
__device__ __forceinline__ void cp16(void* s, const void* g) {
    unsigned sa = (unsigned)__cvta_generic_to_shared(s);
    asm volatile("cp.async.cg.shared.global [%0], [%1], 16;\n" :: "r"(sa), "l"(g));
}
__device__ __forceinline__ void cp4(void* s, const void* g) {
    unsigned sa = (unsigned)__cvta_generic_to_shared(s);
    asm volatile("cp.async.ca.shared.global [%0], [%1], 4;\n" :: "r"(sa), "l"(g));
}
#define CP_COMMIT() asm volatile("cp.async.commit_group;\n" ::: "memory")
#define CP_WAIT(n)  asm volatile("cp.async.wait_group %0;\n" :: "n"(n) : "memory")

// ---------------------------------------------------------------------------
// K0: aq = act(addresses), si = sigmoid(interpolation_logits)
// ---------------------------------------------------------------------------
__global__ void prep_kernel(const float* __restrict__ addresses,
                            const float* __restrict__ interp) {
    int i = blockIdx.x * blockDim.x + threadIdx.x;
    if (i < NM * DMEM) {
        g_aq[i] = actf(addresses[i]);
        g_si[i] = sigm(interp[i]);
    }
}

// ---------------------------------------------------------------------------
// K0b: activations -> bf16
// ---------------------------------------------------------------------------
__global__ void aconv_kernel(const float* __restrict__ key,
                             const float* __restrict__ values) {
    int i = blockIdx.x * blockDim.x + threadIdx.x;
    if (i < NB * DMODEL) {
        g_kb[i] = __float2bfloat16(key[i]);
        g_vb[i] = __float2bfloat16(values[i]);
    }
}

// ---------------------------------------------------------------------------
// K0c: W [DMODEL][N] fp32 -> WT [N][DMODEL] bf16 (tiled transpose)
// ---------------------------------------------------------------------------
__global__ void wconv_kernel(const float* __restrict__ W,
                             __nv_bfloat16* __restrict__ WT, int N) {
    __shared__ float tile[32][33];
    int n0 = blockIdx.x * 32, k0 = blockIdx.y * 32;
    int tx = threadIdx.x, ty = threadIdx.y;   // 32 x 8
    #pragma unroll
    for (int i = 0; i < 4; i++)
        tile[ty + 8 * i][tx] = W[(size_t)(k0 + ty + 8 * i) * N + n0 + tx];
    __syncthreads();
    #pragma unroll
    for (int i = 0; i < 4; i++)
        WT[(size_t)(n0 + ty + 8 * i) * DMODEL + k0 + tx] =
            __float2bfloat16(tile[tx][ty + 8 * i]);
}

// ---------------------------------------------------------------------------
// K1: fused projection GEMMs via mma.sync bf16 (m16n8k16)
//   BM=64 BN=64 BK=32, 256 threads (8 warps, 2x4), warp tile 32x16.
//   Both A and B(=W^T) are k-contiguous bf16 -> every fragment register is
//   ONE aligned 32-bit LDS. Halves smem bytes (R16 analysis: proj was
//   smem/L2 BYTE bound at ~54us smem + ~34us L2) and L2 traffic.
//   3-stage cp.async pipeline (2 tiles in flight), row stride 80B
//   (20 words: lanes 20g+tg all distinct mod 32 -> conflict-free).
// ---------------------------------------------------------------------------
#define BM 64
#define BN 64
#define BK 32
#define ROWB 40          // bf16 elements per smem row: 32 data + 8 pad = 80B
#define PSTG 3

__global__ __launch_bounds__(256, 3) void proj_mma_kernel(
    const float* __restrict__ b_key, const float* __restrict__ b_val)
{
    const __nv_bfloat16 *A, *WT;
    const float* bias;
    float* C;
    int N, doact;
    int bx = blockIdx.x;
    if (bx < KPROJ_N / BN) { A = g_kb; WT = g_WkT; bias = b_key; C = g_ak; N = KPROJ_N; doact = 1; }
    else { bx -= KPROJ_N / BN; A = g_vb; WT = g_WvT; bias = b_val; C = g_v; N = VPROJ_N; doact = 0; }

    __shared__ __nv_bfloat16 As[PSTG][BM][ROWB];   // [stage][m][k]
    __shared__ __nv_bfloat16 Bs[PSTG][BN][ROWB];   // [stage][n][k]

    int t = threadIdx.x;
    int lane = t & 31;
    int warp = t >> 5;
    int g  = lane >> 2;
    int tg = lane & 3;
    int wm = (warp & 1) * 32;
    int wn = (warp >> 1) * 16;
    int bm0 = blockIdx.y * BM;
    int bn0 = bx * BN;

    float acc[2][2][4];
    #pragma unroll
    for (int i = 0; i < 2; i++)
        #pragma unroll
        for (int j = 0; j < 2; j++)
            #pragma unroll
            for (int r = 0; r < 4; r++) acc[i][j][r] = 0.f;

    int row = t >> 2;                 // 0..63
    int chk = (t & 3) * 8;            // bf16 col offset: 0,8,16,24

    const __nv_bfloat16* Ab = A  + (size_t)(bm0 + row) * DMODEL + chk;
    const __nv_bfloat16* Wb = WT + (size_t)(bn0 + row) * DMODEL + chk;
    const int NKT = DMODEL / BK;      // 64

    // prologue: stages 0..PSTG-2
    #pragma unroll
    for (int s = 0; s < PSTG - 1; s++) {
        int k0 = s * BK;
        cp16(&As[s][row][chk], Ab + k0);
        cp16(&Bs[s][row][chk], Wb + k0);
        CP_COMMIT();
    }

    for (int kt = 0; kt < NKT; kt++) {
        CP_WAIT(PSTG - 2);       // tile kt has arrived (one tile still in flight)
        __syncthreads();

        int kp = kt + PSTG - 1;
        if (kp < NKT) {
            int sp = kp % PSTG;
            int k0 = kp * BK;
            cp16(&As[sp][row][chk], Ab + k0);
            cp16(&Bs[sp][row][chk], Wb + k0);
        }
        CP_COMMIT();

        int buf = kt % PSTG;
        #pragma unroll
        for (int ks = 0; ks < 2; ks++) {
            int kk = ks * 16 + 2 * tg;
            unsigned a[2][4], b[2][2];
            #pragma unroll
            for (int ms = 0; ms < 2; ms++) {
                int m = wm + ms * 16 + g;
                a[ms][0] = *(const unsigned*)&As[buf][m    ][kk    ];
                a[ms][1] = *(const unsigned*)&As[buf][m + 8][kk    ];
                a[ms][2] = *(const unsigned*)&As[buf][m    ][kk + 8];
                a[ms][3] = *(const unsigned*)&As[buf][m + 8][kk + 8];
            }
            #pragma unroll
            for (int ns = 0; ns < 2; ns++) {
                int n = wn + ns * 8 + g;
                b[ns][0] = *(const unsigned*)&Bs[buf][n][kk    ];
                b[ns][1] = *(const unsigned*)&Bs[buf][n][kk + 8];
            }
            #pragma unroll
            for (int ms = 0; ms < 2; ms++)
                #pragma unroll
                for (int ns = 0; ns < 2; ns++) {
                    asm volatile(
                        "mma.sync.aligned.m16n8k16.row.col.f32.bf16.bf16.f32 "
                        "{%0,%1,%2,%3}, {%4,%5,%6,%7}, {%8,%9}, {%0,%1,%2,%3};\n"
                        : "+f"(acc[ms][ns][0]), "+f"(acc[ms][ns][1]),
                          "+f"(acc[ms][ns][2]), "+f"(acc[ms][ns][3])
                        : "r"(a[ms][0]), "r"(a[ms][1]), "r"(a[ms][2]), "r"(a[ms][3]),
                          "r"(b[ns][0]), "r"(b[ns][1]));
                }
        }
    }

    #pragma unroll
    for (int ms = 0; ms < 2; ms++) {
        int row0 = bm0 + wm + ms * 16 + g;
        #pragma unroll
        for (int ns = 0; ns < 2; ns++) {
            int col = bn0 + wn + ns * 8 + 2 * tg;
            float b0 = bias[col], b1 = bias[col + 1];
            float o0 = acc[ms][ns][0] + b0;
            float o1 = acc[ms][ns][1] + b1;
            float o2 = acc[ms][ns][2] + b0;
            float o3 = acc[ms][ns][3] + b1;
            if (doact) { o0 = actf(o0); o1 = actf(o1); o2 = actf(o2); o3 = actf(o3); }
            float2 lo = {o0, o1}, hi = {o2, o3};
            *(float2*)(C + (size_t)row0 * N + col)       = lo;
            *(float2*)(C + (size_t)(row0 + 8) * N + col) = hi;
        }
    }
}

// ---------------------------------------------------------------------------
// K2: S[b,m,h] = sum_d aq[m,d] * ak[b,h,d]
// ---------------------------------------------------------------------------
__global__ __launch_bounds__(256) void s_kernel() {
    int b  = blockIdx.y;
    int m0 = blockIdx.x * 32;
    __shared__ float ak_s[8][132];
    __shared__ float aq_s[32][132];
    int t = threadIdx.x;
    {
        int h = t >> 5, d4 = (t & 31) * 4;
        float4 v = *(const float4*)&g_ak[b * KPROJ_N + h * DMEM + d4];
        *(float4*)&ak_s[h][d4] = v;
    }
    #pragma unroll
    for (int i = 0; i < 4; i++) {
        int idx = t + i * 256;
        int ml = idx >> 5, d4 = (idx & 31) * 4;
        float4 v = *(const float4*)&g_aq[(m0 + ml) * DMEM + d4];
        *(float4*)&aq_s[ml][d4] = v;
    }
    __syncthreads();
    int ml = t >> 3, h = t & 7;
    float s = 0.f;
    #pragma unroll
    for (int d4 = 0; d4 < 32; d4++) {
        float4 a = *(const float4*)&aq_s[ml][d4 * 4];
        float4 k = *(const float4*)&ak_s[h][d4 * 4];
        s += a.x * k.x + a.y * k.y + a.z * k.z + a.w * k.w;
    }
    g_S[(b * NM + m0 + ml) * NH + h] = s;
}

// ---------------------------------------------------------------------------
// K3: epilogue (frozen: 96us, occ ~33%, DRAM 66.7%)
// ---------------------------------------------------------------------------
__global__ __launch_bounds__(256, 3) void epilogue_kernel(
    const float* __restrict__ memories, const float* __restrict__ write_mass,
    const unsigned char* __restrict__ batch_mask, float* __restrict__ out)
{
    int b  = blockIdx.y;
    int m0 = blockIdx.x * 32;
    __shared__ float4 v_s[NH * 64];      // 8 KB  v[h][e4]
    __shared__ float  S_s[256];          // 1 KB  S[row*8+h]
    __shared__ float4 si_s[32 * 32];     // 16 KB [row][d4]
    __shared__ float4 mem_s[32 * 32];    // 16 KB
    __shared__ float4 wm_s [32 * 32];    // 16 KB
    int t = threadIdx.x;
    int ml = t >> 5;
    int d4 = t & 31;
    int r0 = ml * 4;

    unsigned char msk = batch_mask[b];

    // group A: v + S + si (needed by compute / wf phase)
    const float4* gv = (const float4*)(g_v + (size_t)b * VPROJ_N);
    cp16(&v_s[t],       &gv[t]);
    cp16(&v_s[t + 256], &gv[t + 256]);
    cp4(&S_s[t], &g_S[((size_t)b * NM + m0) * NH + t]);
    #pragma unroll
    for (int i = 0; i < 4; i++) {
        int row = r0 + i;
        cp16(&si_s[row * 32 + d4], &g_si[(m0 + row) * DMEM + d4 * 4]);
    }
    CP_COMMIT();

    // group B: memories + write_mass (needed only at tail)
    #pragma unroll
    for (int i = 0; i < 4; i++) {
        int row = r0 + i;
        size_t base = ((size_t)b * NM + m0 + row) * DMEM + d4 * 4;
        cp16(&mem_s[row * 32 + d4], &memories[base]);
        cp16(&wm_s [row * 32 + d4], &write_mass[base]);
    }
    CP_COMMIT();

    CP_WAIT(1);          // group A done
    __syncthreads();

    float dn[4] = {1e-5f, 1e-5f, 1e-5f, 1e-5f};

    // pass 1: write-logit accumulation (reads only lower half of v)
    float4 aL[4];
    #pragma unroll
    for (int i = 0; i < 4; i++) aL[i] = make_float4(0.f, 0.f, 0.f, 0.f);
    #pragma unroll
    for (int h = 0; h < 8; h++) {
        float4 vl = v_s[h * 64 + 32 + d4];
        #pragma unroll
        for (int i = 0; i < 4; i++) {
            float s = S_s[(r0 + i) * 8 + h];
            dn[i] += s;
            aL[i].x = fmaf(s, vl.x, aL[i].x); aL[i].y = fmaf(s, vl.y, aL[i].y);
            aL[i].z = fmaf(s, vl.z, aL[i].z); aL[i].w = fmaf(s, vl.w, aL[i].w);
        }
    }

    // wf (aL registers die here)
    float rdv[4];
    float4 wf[4];
    #pragma unroll
    for (int i = 0; i < 4; i++) {
        rdv[i] = __fdividef(1.f, dn[i]);
        float4 si = si_s[(r0 + i) * 32 + d4];
        wf[i].x = 0.7f * sigm(aL[i].x * rdv[i]) * si.x;
        wf[i].y = 0.7f * sigm(aL[i].y * rdv[i]) * si.y;
        wf[i].z = 0.7f * sigm(aL[i].z * rdv[i]) * si.z;
        wf[i].w = 0.7f * sigm(aL[i].w * rdv[i]) * si.w;
    }

    // pass 2: update accumulation (reads only upper half of v)
    float4 aU[4];
    #pragma unroll
    for (int i = 0; i < 4; i++) aU[i] = make_float4(0.f, 0.f, 0.f, 0.f);
    #pragma unroll
    for (int h = 0; h < 8; h++) {
        float4 vu = v_s[h * 64 + d4];
        #pragma unroll
        for (int i = 0; i < 4; i++) {
            float s = S_s[(r0 + i) * 8 + h];
            aU[i].x = fmaf(s, vu.x, aU[i].x); aU[i].y = fmaf(s, vu.y, aU[i].y);
            aU[i].z = fmaf(s, vu.z, aU[i].z); aU[i].w = fmaf(s, vu.w, aU[i].w);
        }
    }

    CP_WAIT(0);          // group B done
    __syncthreads();

    #pragma unroll
    for (int i = 0; i < 4; i++) {
        int row = r0 + i;
        size_t base = ((size_t)b * NM + m0 + row) * DMEM + d4 * 4;
        float4 mem = mem_s[row * 32 + d4];
        float4 wm4 = wm_s [row * 32 + d4];

        float4 om, oa;
        if (msk) {
            om = mem; oa = wm4;
        } else {
            om.x = mem.x + wf[i].x * (aU[i].x * rdv[i] - mem.x);
            om.y = mem.y + wf[i].y * (aU[i].y * rdv[i] - mem.y);
            om.z = mem.z + wf[i].z * (aU[i].z * rdv[i] - mem.z);
            om.w = mem.w + wf[i].w * (aU[i].w * rdv[i] - mem.w);
            oa.x = wm4.x + wf[i].x; oa.y = wm4.y + wf[i].y;
            oa.z = wm4.z + wf[i].z; oa.w = wm4.w + wf[i].w;
        }
        *(float4*)&out[base] = om;
        *(float4*)&out[MEM_ELEMS + base] = oa;
    }
}

// ---------------------------------------------------------------------------
extern "C" void kernel_launch(void* const* d_in, const int* in_sizes, int n_in,
                              void* d_out, int out_size) {
    const float* key        = (const float*)d_in[0];
    const float* values     = (const float*)d_in[1];
    const float* memories   = (const float*)d_in[2];
    const float* write_mass = (const float*)d_in[3];
    const unsigned char* batch_mask = (const unsigned char*)d_in[4];
    const float* W_key      = (const float*)d_in[5];
    const float* b_key      = (const float*)d_in[6];
    const float* W_val      = (const float*)d_in[7];
    const float* b_val      = (const float*)d_in[8];
    const float* addresses  = (const float*)d_in[9];
    const float* interp     = (const float*)d_in[10];
    float* out = (float*)d_out;

    __nv_bfloat16* wkT;
    __nv_bfloat16* wvT;
    cudaGetSymbolAddress((void**)&wkT, g_WkT);
    cudaGetSymbolAddress((void**)&wvT, g_WvT);

    prep_kernel<<<256, 256>>>(addresses, interp);
    aconv_kernel<<<(NB * DMODEL + 255) / 256, 256>>>(key, values);
    wconv_kernel<<<dim3(KPROJ_N / 32, DMODEL / 32), dim3(32, 8)>>>(W_key, wkT, KPROJ_N);
    wconv_kernel<<<dim3(VPROJ_N / 32, DMODEL / 32), dim3(32, 8)>>>(W_val, wvT, VPROJ_N);
    proj_mma_kernel<<<dim3((KPROJ_N + VPROJ_N) / BN, NB / BM), 256>>>(b_key, b_val);
    s_kernel<<<dim3(NM / 32, NB), 256>>>();
    epilogue_kernel<<<dim3(NM / 32, NB), 256>>>(memories, write_mass, batch_mask, out);
}